// round 2
// baseline (speedup 1.0000x reference)
#include <cuda_runtime.h>
#include <cstddef>

#define S_LEN 4096
#define D_IN  512
#define K_MEM 256
#define N_HID 1024
#define BATCH 8
#define KDIM  (K_MEM + D_IN)          // 768
#define M_ROWS (BATCH * S_LEN)        // 32768
#define TPT 16                        // t-values per thread in conv

// ---------------- scratch (static device memory; no allocations) ----------------
__device__ float g_u[M_ROWS];                       // relu(x . w_u) per (b,t)
__device__ float g_At[(size_t)KDIM * M_ROWS];       // column-major A: At[k*M + (b*S+t)]
                                                    // k<256: conv output m; k>=256: x transposed

// ---------------- kernel 1: u = relu(x @ w + b), one warp per row ----------------
__global__ void k_u(const float* __restrict__ x, const float* __restrict__ w,
                    const float* __restrict__ bias) {
    int R = blockIdx.x * 8 + (threadIdx.x >> 5);
    int lane = threadIdx.x & 31;
    const float4* xr = (const float4*)(x + (size_t)R * D_IN);
    const float4* wv = (const float4*)w;
    float s = 0.f;
#pragma unroll
    for (int j = 0; j < 4; j++) {
        float4 a = xr[lane + 32 * j];
        float4 b = wv[lane + 32 * j];
        s += a.x * b.x + a.y * b.y + a.z * b.z + a.w * b.w;
    }
#pragma unroll
    for (int o = 16; o; o >>= 1) s += __shfl_xor_sync(0xffffffffu, s, o);
    if (lane == 0) g_u[R] = fmaxf(s + bias[0], 0.f);
}

// ---------------- kernel 2: transpose x into At rows [256..768) ----------------
__global__ void k_xT(const float* __restrict__ x) {
    __shared__ float s[32][33];
    int R0 = blockIdx.x * 32;
    int d0 = blockIdx.y * 32;
    int tx = threadIdx.x & 31;
    int ty = threadIdx.x >> 5;     // 0..7
#pragma unroll
    for (int i = 0; i < 4; i++) {
        int r = ty + i * 8;
        s[r][tx] = x[(size_t)(R0 + r) * D_IN + d0 + tx];
    }
    __syncthreads();
#pragma unroll
    for (int i = 0; i < 4; i++) {
        int d = ty + i * 8;
        g_At[(size_t)(K_MEM + d0 + d) * M_ROWS + R0 + tx] = s[tx][d];
    }
}

// ---------------- kernel 3: causal conv m[b,t,k] = sum_lag H[k,lag]*u[b,t-lag] ----------------
// Block = (k, b). u row + H row in SMEM. Thread computes 16 consecutive t via a
// rolling 16-register circular window over u. u stored padded (+1 word per 16) to
// avoid 16-way bank conflicts on stride-16 lane access; 16 leading zeros avoid
// tail predication (negative u indices read zero).
__global__ void __launch_bounds__(256) k_conv(const float* __restrict__ H) {
    __shared__ float Hs[S_LEN];
    __shared__ float us[4368];   // PAD(j)=j+(j>>4), max jj=4111 -> 4367
    int k = blockIdx.x;
    int b = blockIdx.y;
    int tid = threadIdx.x;

    for (int j = tid; j < S_LEN; j += 256) Hs[j] = H[(size_t)k * S_LEN + j];
    if (tid < 16) us[tid + (tid >> 4)] = 0.f;                      // u[-16..-1] = 0
    for (int j = tid; j < S_LEN; j += 256) {
        int jj = j + 16;
        us[jj + (jj >> 4)] = g_u[b * S_LEN + j];
    }
    __syncthreads();

    int t0 = tid * TPT;
    float acc[TPT];
    float W[TPT];                 // circular: W[(r - lag) & 15] = u[t0 + r - lag]
#pragma unroll
    for (int r = 0; r < TPT; r++) {
        acc[r] = 0.f;
        int jj = t0 + r + 16;
        W[r] = us[jj + (jj >> 4)];            // lag = 0 window
    }

    // address induction for refill loads: first refill is u[t0-1] -> jj = t0+15
    int ua = (t0 + 15) + ((t0 + 15) >> 4);
    int Lmax = t0 + TPT;                       // multiple of 16

    for (int LB = 0; LB < Lmax; LB += 16) {
#pragma unroll
        for (int li = 0; li < 16; li++) {
            float hv = Hs[LB + li];
#pragma unroll
            for (int r = 0; r < TPT; r++)
                acc[r] = fmaf(hv, W[(r - li) & 15], acc[r]);
            // fetch u[t0 - (lag+1)] into slot (15 - li)  (lag = LB + li)
            W[15 - li] = us[ua];
            ua -= (li == 15) ? 2 : 1;          // padded-address induction
        }
    }

    size_t obase = (size_t)k * M_ROWS + (size_t)b * S_LEN + t0;
#pragma unroll
    for (int r = 0; r < TPT; r++) g_At[obase + r] = acc[r];
}

// ---------------- kernel 4: h = relu(A @ W^T + b); A = g_At (col-major), W = (1024x768) ----------------
#define BM 128
#define BN 128
#define BK 16
__global__ void __launch_bounds__(256) k_gemm(const float* __restrict__ Wh,
                                              const float* __restrict__ bh,
                                              float* __restrict__ out, long long out_size) {
    __shared__ float As[BK][132];
    __shared__ float Bs[BK][132];
    int n0 = blockIdx.x * BN;
    int R0 = blockIdx.y * BM;
    int tid = threadIdx.x;
    int tx = tid & 15;             // n direction
    int ty = tid >> 4;             // t direction
    float acc[8][8];
#pragma unroll
    for (int i = 0; i < 8; i++)
#pragma unroll
        for (int j = 0; j < 8; j++) acc[i][j] = 0.f;

    int la_k = tid >> 5;           // 0..7 (+8 for second row)
    int la_t = (tid & 31) << 2;    // 0..124
    int lb_n = tid >> 1;           // 0..127
    int lb_k = (tid & 1) << 3;     // 0 or 8

    for (int k0 = 0; k0 < KDIM; k0 += BK) {
#pragma unroll
        for (int h = 0; h < 2; h++) {
            int kk = la_k + h * 8;
            float4 v = *(const float4*)&g_At[(size_t)(k0 + kk) * M_ROWS + R0 + la_t];
            *(float4*)&As[kk][la_t] = v;
        }
        {
            const float* wp = &Wh[(size_t)(n0 + lb_n) * KDIM + k0 + lb_k];
            float4 v0 = *(const float4*)wp;
            float4 v1 = *(const float4*)(wp + 4);
            Bs[lb_k + 0][lb_n] = v0.x; Bs[lb_k + 1][lb_n] = v0.y;
            Bs[lb_k + 2][lb_n] = v0.z; Bs[lb_k + 3][lb_n] = v0.w;
            Bs[lb_k + 4][lb_n] = v1.x; Bs[lb_k + 5][lb_n] = v1.y;
            Bs[lb_k + 6][lb_n] = v1.z; Bs[lb_k + 7][lb_n] = v1.w;
        }
        __syncthreads();
#pragma unroll
        for (int kk = 0; kk < BK; kk++) {
            float a[8], bb[8];
            *(float4*)&a[0] = *(const float4*)&As[kk][ty * 4];
            *(float4*)&a[4] = *(const float4*)&As[kk][64 + ty * 4];
            *(float4*)&bb[0] = *(const float4*)&Bs[kk][tx * 4];
            *(float4*)&bb[4] = *(const float4*)&Bs[kk][64 + tx * 4];
#pragma unroll
            for (int i = 0; i < 8; i++)
#pragma unroll
                for (int j = 0; j < 8; j++)
                    acc[i][j] = fmaf(a[i], bb[j], acc[i][j]);
        }
        __syncthreads();
    }

    // epilogue: bias + relu, write h; rows with t == S-1 also write h_last tail
#pragma unroll
    for (int i = 0; i < 8; i++) {
        int R = R0 + ((i < 4) ? (ty * 4 + i) : (64 + ty * 4 + (i - 4)));
#pragma unroll
        for (int jh = 0; jh < 2; jh++) {
            int n = n0 + jh * 64 + tx * 4;
            float4 v;
            v.x = fmaxf(acc[i][jh * 4 + 0] + bh[n + 0], 0.f);
            v.y = fmaxf(acc[i][jh * 4 + 1] + bh[n + 1], 0.f);
            v.z = fmaxf(acc[i][jh * 4 + 2] + bh[n + 2], 0.f);
            v.w = fmaxf(acc[i][jh * 4 + 3] + bh[n + 3], 0.f);
            *(float4*)&out[(size_t)R * N_HID + n] = v;
            if ((R & (S_LEN - 1)) == (S_LEN - 1)) {
                int b = R >> 12;
                long long tidx = (long long)M_ROWS * N_HID + (long long)b * N_HID + n;
                if (tidx + 3 < out_size) *(float4*)&out[tidx] = v;
            }
        }
    }
}

// ---------------- launch ----------------
extern "C" void kernel_launch(void* const* d_in, const int* in_sizes, int n_in,
                              void* d_out, int out_size) {
    // identify inputs by element count (all distinct)
    const float *x = nullptr, *Wuw = nullptr, *Wub = nullptr, *Whw = nullptr,
                *Whb = nullptr, *H = nullptr;
    for (int i = 0; i < n_in; i++) {
        switch (in_sizes[i]) {
            case 16777216: x   = (const float*)d_in[i]; break;  // 8*4096*512
            case 512:      Wuw = (const float*)d_in[i]; break;
            case 1:        Wub = (const float*)d_in[i]; break;
            case 786432:   Whw = (const float*)d_in[i]; break;  // 1024*768
            case 1024:     Whb = (const float*)d_in[i]; break;
            case 1048576:  H   = (const float*)d_in[i]; break;  // 256*4096
        }
    }
    float* out = (float*)d_out;

    k_u  <<<M_ROWS / 8, 256>>>(x, Wuw, Wub);
    k_xT <<<dim3(M_ROWS / 32, D_IN / 32), 256>>>(x);
    k_conv<<<dim3(K_MEM, BATCH), 256>>>(H);
    k_gemm<<<dim3(N_HID / BN, M_ROWS / BM), 256>>>(Whw, Whb, out, (long long)out_size);
}

// round 5
// speedup vs baseline: 1.3611x; 1.3611x over previous
#include <cuda_runtime.h>
#include <cuda_bf16.h>
#include <cstdint>
#include <cstddef>

#define S_LEN 4096
#define D_IN  512
#define K_MEM 256
#define N_HID 1024
#define BATCH 8
#define KDIM  (K_MEM + D_IN)          // 768
#define M_ROWS (BATCH * S_LEN)        // 32768
#define TPT 16

// ---------------- scratch (static device memory; no allocations) ----------------
__device__ float g_u[M_ROWS];
__device__ float g_m[(size_t)K_MEM * M_ROWS];            // conv out, [k][m]
__device__ __nv_bfloat16 g_Ah[(size_t)M_ROWS * KDIM];    // A hi, [m][k]
__device__ __nv_bfloat16 g_Al[(size_t)M_ROWS * KDIM];    // A lo
__device__ __nv_bfloat16 g_Wh[(size_t)N_HID * KDIM];     // W hi, [n][k]
__device__ __nv_bfloat16 g_Wl[(size_t)N_HID * KDIM];     // W lo

// ---------------- helpers ----------------
__device__ __forceinline__ uint32_t smem_u32(const void* p) {
    uint32_t a;
    asm("{ .reg .u64 t; cvta.to.shared.u64 t, %1; cvt.u32.u64 %0, t; }" : "=r"(a) : "l"(p));
    return a;
}
#define CP_ASYNC16(dst, src) \
    asm volatile("cp.async.cg.shared.global [%0], [%1], 16;" :: "r"(dst), "l"(src) : "memory")
#define CP_COMMIT()  asm volatile("cp.async.commit_group;" ::: "memory")
#define CP_WAIT0()   asm volatile("cp.async.wait_group 0;" ::: "memory")
#define LDSM_X4(r0, r1, r2, r3, addr) \
    asm volatile("ldmatrix.sync.aligned.m8n8.x4.shared.b16 {%0,%1,%2,%3}, [%4];" \
                 : "=r"(r0), "=r"(r1), "=r"(r2), "=r"(r3) : "r"(addr))
#define MMA16816(d, a, b0, b1) \
    asm volatile("mma.sync.aligned.m16n8k16.row.col.f32.bf16.bf16.f32 " \
                 "{%0,%1,%2,%3}, {%4,%5,%6,%7}, {%8,%9}, {%0,%1,%2,%3};" \
                 : "+f"((d)[0]), "+f"((d)[1]), "+f"((d)[2]), "+f"((d)[3]) \
                 : "r"((a)[0]), "r"((a)[1]), "r"((a)[2]), "r"((a)[3]), "r"(b0), "r"(b1))

// ---------------- kernel 1: u = relu(x @ w + b) ----------------
__global__ void k_u(const float* __restrict__ x, const float* __restrict__ w,
                    const float* __restrict__ bias) {
    int R = blockIdx.x * 8 + (threadIdx.x >> 5);
    int lane = threadIdx.x & 31;
    const float4* xr = (const float4*)(x + (size_t)R * D_IN);
    const float4* wv = (const float4*)w;
    float s = 0.f;
#pragma unroll
    for (int j = 0; j < 4; j++) {
        float4 a = xr[lane + 32 * j];
        float4 b = wv[lane + 32 * j];
        s += a.x * b.x + a.y * b.y + a.z * b.z + a.w * b.w;
    }
#pragma unroll
    for (int o = 16; o; o >>= 1) s += __shfl_xor_sync(0xffffffffu, s, o);
    if (lane == 0) g_u[R] = fmaxf(s + bias[0], 0.f);
}

// ---------------- kernel 2: causal conv (verified) ----------------
__global__ void __launch_bounds__(256) k_conv(const float* __restrict__ H) {
    __shared__ float Hs[S_LEN];
    __shared__ float us[4368];
    int k = blockIdx.x, b = blockIdx.y, tid = threadIdx.x;

    for (int j = tid; j < S_LEN; j += 256) Hs[j] = H[(size_t)k * S_LEN + j];
    if (tid < 16) us[tid + (tid >> 4)] = 0.f;
    for (int j = tid; j < S_LEN; j += 256) {
        int jj = j + 16;
        us[jj + (jj >> 4)] = g_u[b * S_LEN + j];
    }
    __syncthreads();

    int t0 = tid * TPT;
    float acc[TPT], W[TPT];
#pragma unroll
    for (int r = 0; r < TPT; r++) {
        acc[r] = 0.f;
        int jj = t0 + r + 16;
        W[r] = us[jj + (jj >> 4)];
    }
    int ua = (t0 + 15) + ((t0 + 15) >> 4);
    int Lmax = t0 + TPT;
    for (int LB = 0; LB < Lmax; LB += 16) {
#pragma unroll
        for (int li = 0; li < 16; li++) {
            float hv = Hs[LB + li];
#pragma unroll
            for (int r = 0; r < TPT; r++)
                acc[r] = fmaf(hv, W[(r - li) & 15], acc[r]);
            W[15 - li] = us[ua];
            ua -= (li == 15) ? 2 : 1;
        }
    }
    size_t obase = (size_t)k * M_ROWS + (size_t)b * S_LEN + t0;
#pragma unroll
    for (int r = 0; r < TPT; r++) g_m[obase + r] = acc[r];
}

// ---------------- kernel 3: transpose-convert conv out -> A hi/lo [m][0..256) ----------------
__global__ void k_cvt_conv() {
    __shared__ float s[32][33];
    int m0 = blockIdx.x * 32, k0 = blockIdx.y * 32;
    int tx = threadIdx.x & 31, ty = threadIdx.x >> 5;
#pragma unroll
    for (int i = 0; i < 4; i++)
        s[ty + i * 8][tx] = g_m[(size_t)(k0 + ty + i * 8) * M_ROWS + m0 + tx];
    __syncthreads();
#pragma unroll
    for (int i = 0; i < 4; i++) {
        int mr = ty + i * 8;
        float v = s[tx][mr];
        __nv_bfloat16 hi = __float2bfloat16(v);
        size_t o = (size_t)(m0 + mr) * KDIM + k0 + tx;
        g_Ah[o] = hi;
        g_Al[o] = __float2bfloat16(v - __bfloat162float(hi));
    }
}

// ---------------- kernel 4: stream-convert x -> A hi/lo [m][256..768) ----------------
__global__ void k_cvt_x(const float* __restrict__ x) {
    int g = blockIdx.x * 256 + threadIdx.x;
    int base = g * 4;
    int m = base >> 9, d = base & 511;
    float4 v = *(const float4*)(x + (size_t)m * D_IN + d);
    size_t o = (size_t)m * KDIM + K_MEM + d;
    __nv_bfloat162 h0 = __floats2bfloat162_rn(v.x, v.y);
    __nv_bfloat162 h1 = __floats2bfloat162_rn(v.z, v.w);
    *(__nv_bfloat162*)&g_Ah[o]     = h0;
    *(__nv_bfloat162*)&g_Ah[o + 2] = h1;
    __nv_bfloat162 l0 = __floats2bfloat162_rn(v.x - __bfloat162float(h0.x),
                                              v.y - __bfloat162float(h0.y));
    __nv_bfloat162 l1 = __floats2bfloat162_rn(v.z - __bfloat162float(h1.x),
                                              v.w - __bfloat162float(h1.y));
    *(__nv_bfloat162*)&g_Al[o]     = l0;
    *(__nv_bfloat162*)&g_Al[o + 2] = l1;
}

// ---------------- kernel 5: stream-convert W ----------------
__global__ void k_cvtW(const float* __restrict__ Wh) {
    int g = blockIdx.x * 256 + threadIdx.x;
    size_t o = (size_t)g * 4;
    float4 v = *(const float4*)(Wh + o);
    __nv_bfloat162 h0 = __floats2bfloat162_rn(v.x, v.y);
    __nv_bfloat162 h1 = __floats2bfloat162_rn(v.z, v.w);
    *(__nv_bfloat162*)&g_Wh[o]     = h0;
    *(__nv_bfloat162*)&g_Wh[o + 2] = h1;
    __nv_bfloat162 l0 = __floats2bfloat162_rn(v.x - __bfloat162float(h0.x),
                                              v.y - __bfloat162float(h0.y));
    __nv_bfloat162 l1 = __floats2bfloat162_rn(v.z - __bfloat162float(h1.x),
                                              v.w - __bfloat162float(h1.y));
    *(__nv_bfloat162*)&g_Wl[o]     = l0;
    *(__nv_bfloat162*)&g_Wl[o + 2] = l1;
}

// ---------------- kernel 6: mma.sync bf16 GEMM, h = relu(A @ W^T + b) ----------------
// CTA 128x128, 8 warps (2M x 4N), warp tile 64x32.  K' = 3*768 = 2304:
// phases Ah*Wh, Ah*Wl, Al*Wh.  K-chunks of 32, cp.async double buffer.
// SMEM rows padded to 80B -> ldmatrix conflict-free (banks 20*row mod 32 distinct).
#define KC 32
#define ROWB 40                      // halves per padded row (80B)
#define BUFB (128 * ROWB)            // halves per buffer
#define NCH 72                       // 3 phases * 24 chunks

__global__ void __launch_bounds__(256) k_mgemm(const float* __restrict__ bias,
                                               float* __restrict__ out, long long out_size) {
    __shared__ __nv_bfloat16 smA[2][BUFB];
    __shared__ __nv_bfloat16 smB[2][BUFB];
    int tid = threadIdx.x, lane = tid & 31, wid = tid >> 5;
    int warpM = wid >> 2, warpN = wid & 3;
    int n0 = blockIdx.x * 128, R0 = blockIdx.y * 128;
    uint32_t aBase = smem_u32(smA), bBase = smem_u32(smB);

    float acc[4][4][4];
#pragma unroll
    for (int i = 0; i < 4; i++)
#pragma unroll
        for (int j = 0; j < 4; j++)
#pragma unroll
            for (int q = 0; q < 4; q++) acc[i][j][q] = 0.f;

    int prow = tid >> 2;            // 0..63? no: tid/4 over 2 iters covers 128 rows
    int pseg = tid & 3;

    // prefetch chunk c into buffer s
    auto prefetch = [&](int c, int s) {
        int p = c / 24, kk = (c % 24) * KC;
        const __nv_bfloat16* As = (p < 2) ? g_Ah : g_Al;
        const __nv_bfloat16* Bs = (p == 1) ? g_Wl : g_Wh;
#pragma unroll
        for (int it = 0; it < 2; it++) {
            int row = prow + it * 64;
            uint32_t da = aBase + (uint32_t)(s * BUFB * 2 + row * 80 + pseg * 16);
            CP_ASYNC16(da, (const void*)(As + (size_t)(R0 + row) * KDIM + kk + pseg * 8));
            uint32_t db = bBase + (uint32_t)(s * BUFB * 2 + row * 80 + pseg * 16);
            CP_ASYNC16(db, (const void*)(Bs + (size_t)(n0 + row) * KDIM + kk + pseg * 8));
        }
    };

    prefetch(0, 0);
    CP_COMMIT();

    int arow = warpM * 64 + (lane & 15);
    int acolh = (lane >> 4) << 3;               // +0 or +8 halves
    int brow = warpN * 32 + ((lane >> 4) << 3) + (lane & 7);
    int bcolh = ((lane >> 3) & 1) << 3;

    for (int c = 0; c < NCH; c++) {
        CP_WAIT0();
        __syncthreads();
        if (c + 1 < NCH) { prefetch(c + 1, (c + 1) & 1); CP_COMMIT(); }
        uint32_t sA = aBase + (uint32_t)((c & 1) * BUFB * 2);
        uint32_t sB = bBase + (uint32_t)((c & 1) * BUFB * 2);
#pragma unroll
        for (int ks = 0; ks < 2; ks++) {
            int k0 = ks * 16;
            uint32_t a[4][4], b[4][2];
#pragma unroll
            for (int mi = 0; mi < 4; mi++) {
                uint32_t ad = sA + (uint32_t)((arow + mi * 16) * 80 + (k0 + acolh) * 2);
                LDSM_X4(a[mi][0], a[mi][1], a[mi][2], a[mi][3], ad);
            }
#pragma unroll
            for (int nj = 0; nj < 2; nj++) {
                uint32_t bd = sB + (uint32_t)((brow + nj * 16) * 80 + (k0 + bcolh) * 2);
                uint32_t r0, r1, r2, r3;
                LDSM_X4(r0, r1, r2, r3, bd);
                b[nj * 2][0] = r0;     b[nj * 2][1] = r1;
                b[nj * 2 + 1][0] = r2; b[nj * 2 + 1][1] = r3;
            }
#pragma unroll
            for (int mi = 0; mi < 4; mi++)
#pragma unroll
                for (int ni = 0; ni < 4; ni++)
                    MMA16816(acc[mi][ni], a[mi], b[ni][0], b[ni][1]);
        }
        __syncthreads();
    }

    // epilogue: d0,d1 at (row = lane/4, col = 2*(lane%3? no %4)), d2,d3 at row+8
    int erow = lane >> 2;
    int ecol = (lane & 3) << 1;
#pragma unroll
    for (int mi = 0; mi < 4; mi++) {
        int m0 = R0 + warpM * 64 + mi * 16 + erow;
#pragma unroll
        for (int ni = 0; ni < 4; ni++) {
            int n = n0 + warpN * 32 + ni * 8 + ecol;
            float b0 = bias[n], b1 = bias[n + 1];
            float2 v0, v1;
            v0.x = fmaxf(acc[mi][ni][0] + b0, 0.f);
            v0.y = fmaxf(acc[mi][ni][1] + b1, 0.f);
            v1.x = fmaxf(acc[mi][ni][2] + b0, 0.f);
            v1.y = fmaxf(acc[mi][ni][3] + b1, 0.f);
            int m1 = m0 + 8;
            *(float2*)&out[(size_t)m0 * N_HID + n] = v0;
            *(float2*)&out[(size_t)m1 * N_HID + n] = v1;
            if ((m0 & (S_LEN - 1)) == (S_LEN - 1)) {
                long long ti = (long long)M_ROWS * N_HID + (long long)(m0 >> 12) * N_HID + n;
                if (ti + 1 < out_size) *(float2*)&out[ti] = v0;
            }
            if ((m1 & (S_LEN - 1)) == (S_LEN - 1)) {
                long long ti = (long long)M_ROWS * N_HID + (long long)(m1 >> 12) * N_HID + n;
                if (ti + 1 < out_size) *(float2*)&out[ti] = v1;
            }
        }
    }
}

// ---------------- launch ----------------
extern "C" void kernel_launch(void* const* d_in, const int* in_sizes, int n_in,
                              void* d_out, int out_size) {
    const float *x = nullptr, *Wuw = nullptr, *Wub = nullptr, *Whw = nullptr,
                *Whb = nullptr, *H = nullptr;
    for (int i = 0; i < n_in; i++) {
        switch (in_sizes[i]) {
            case 16777216: x   = (const float*)d_in[i]; break;
            case 512:      Wuw = (const float*)d_in[i]; break;
            case 1:        Wub = (const float*)d_in[i]; break;
            case 786432:   Whw = (const float*)d_in[i]; break;
            case 1024:     Whb = (const float*)d_in[i]; break;
            case 1048576:  H   = (const float*)d_in[i]; break;
        }
    }
    float* out = (float*)d_out;

    k_u       <<<M_ROWS / 8, 256>>>(x, Wuw, Wub);
    k_cvt_x   <<<M_ROWS * D_IN / 4 / 256, 256>>>(x);
    k_cvtW    <<<N_HID * KDIM / 4 / 256, 256>>>(Whw);
    k_conv    <<<dim3(K_MEM, BATCH), 256>>>(H);
    k_cvt_conv<<<dim3(M_ROWS / 32, K_MEM / 32), 256>>>();
    k_mgemm   <<<dim3(N_HID / 128, M_ROWS / 128), 256>>>(Whb, out, (long long)out_size);
}

// round 6
// speedup vs baseline: 1.9845x; 1.4581x over previous
#include <cuda_runtime.h>
#include <cuda_bf16.h>
#include <cstdint>
#include <cstddef>

#define S_LEN 4096
#define D_IN  512
#define K_MEM 256
#define N_HID 1024
#define BATCH 8
#define KDIM  (K_MEM + D_IN)          // 768
#define M_ROWS (BATCH * S_LEN)        // 32768

// ---------------- scratch (static device memory; no allocations) ----------------
__device__ float g_u[M_ROWS];
__device__ __nv_bfloat16 g_Ah[(size_t)M_ROWS * KDIM];    // A hi, [m][k]
__device__ __nv_bfloat16 g_Al[(size_t)M_ROWS * KDIM];    // A lo
__device__ __nv_bfloat16 g_Wh[(size_t)N_HID * KDIM];     // W hi, [n][k]
__device__ __nv_bfloat16 g_Wl[(size_t)N_HID * KDIM];     // W lo
__device__ __nv_bfloat16 g_Hh[(size_t)K_MEM * S_LEN];    // H hi, [k][lag]
__device__ __nv_bfloat16 g_Hl[(size_t)K_MEM * S_LEN];    // H lo

// ---------------- helpers ----------------
__device__ __forceinline__ uint32_t smem_u32(const void* p) {
    uint32_t a;
    asm("{ .reg .u64 t; cvta.to.shared.u64 t, %1; cvt.u32.u64 %0, t; }" : "=r"(a) : "l"(p));
    return a;
}
#define CP_ASYNC16(dst, src) \
    asm volatile("cp.async.cg.shared.global [%0], [%1], 16;" :: "r"(dst), "l"(src) : "memory")
#define CP_COMMIT()  asm volatile("cp.async.commit_group;" ::: "memory")
#define CP_WAIT0()   asm volatile("cp.async.wait_group 0;" ::: "memory")
#define LDSM_X4(r0, r1, r2, r3, addr) \
    asm volatile("ldmatrix.sync.aligned.m8n8.x4.shared.b16 {%0,%1,%2,%3}, [%4];" \
                 : "=r"(r0), "=r"(r1), "=r"(r2), "=r"(r3) : "r"(addr))
#define MMA16816(d, a, b0, b1) \
    asm volatile("mma.sync.aligned.m16n8k16.row.col.f32.bf16.bf16.f32 " \
                 "{%0,%1,%2,%3}, {%4,%5,%6,%7}, {%8,%9}, {%0,%1,%2,%3};" \
                 : "+f"((d)[0]), "+f"((d)[1]), "+f"((d)[2]), "+f"((d)[3]) \
                 : "r"((a)[0]), "r"((a)[1]), "r"((a)[2]), "r"((a)[3]), "r"(b0), "r"(b1))

// ---------------- kernel 1: u = relu(x @ w + b) ----------------
__global__ void k_u(const float* __restrict__ x, const float* __restrict__ w,
                    const float* __restrict__ bias) {
    int R = blockIdx.x * 8 + (threadIdx.x >> 5);
    int lane = threadIdx.x & 31;
    const float4* xr = (const float4*)(x + (size_t)R * D_IN);
    const float4* wv = (const float4*)w;
    float s = 0.f;
#pragma unroll
    for (int j = 0; j < 4; j++) {
        float4 a = xr[lane + 32 * j];
        float4 b = wv[lane + 32 * j];
        s += a.x * b.x + a.y * b.y + a.z * b.z + a.w * b.w;
    }
#pragma unroll
    for (int o = 16; o; o >>= 1) s += __shfl_xor_sync(0xffffffffu, s, o);
    if (lane == 0) g_u[R] = fmaxf(s + bias[0], 0.f);
}

// ---------------- kernel 2: generic fp32 -> bf16 hi/lo split ----------------
__global__ void k_split(const float* __restrict__ src, __nv_bfloat16* __restrict__ dh,
                        __nv_bfloat16* __restrict__ dl) {
    size_t o = ((size_t)blockIdx.x * 256 + threadIdx.x) * 4;
    float4 v = *(const float4*)(src + o);
    __nv_bfloat162 h0 = __floats2bfloat162_rn(v.x, v.y);
    __nv_bfloat162 h1 = __floats2bfloat162_rn(v.z, v.w);
    *(__nv_bfloat162*)&dh[o]     = h0;
    *(__nv_bfloat162*)&dh[o + 2] = h1;
    __nv_bfloat162 l0 = __floats2bfloat162_rn(v.x - __bfloat162float(h0.x),
                                              v.y - __bfloat162float(h0.y));
    __nv_bfloat162 l1 = __floats2bfloat162_rn(v.z - __bfloat162float(h1.x),
                                              v.w - __bfloat162float(h1.y));
    *(__nv_bfloat162*)&dl[o]     = l0;
    *(__nv_bfloat162*)&dl[o + 2] = l1;
}

// ---------------- kernel 3: stream-convert x -> A hi/lo [m][256..768) ----------------
__global__ void k_cvt_x(const float* __restrict__ x) {
    int g = blockIdx.x * 256 + threadIdx.x;
    int base = g * 4;
    int m = base >> 9, d = base & 511;
    float4 v = *(const float4*)(x + (size_t)m * D_IN + d);
    size_t o = (size_t)m * KDIM + K_MEM + d;
    __nv_bfloat162 h0 = __floats2bfloat162_rn(v.x, v.y);
    __nv_bfloat162 h1 = __floats2bfloat162_rn(v.z, v.w);
    *(__nv_bfloat162*)&g_Ah[o]     = h0;
    *(__nv_bfloat162*)&g_Ah[o + 2] = h1;
    __nv_bfloat162 l0 = __floats2bfloat162_rn(v.x - __bfloat162float(h0.x),
                                              v.y - __bfloat162float(h0.y));
    __nv_bfloat162 l1 = __floats2bfloat162_rn(v.z - __bfloat162float(h1.x),
                                              v.w - __bfloat162float(h1.y));
    *(__nv_bfloat162*)&g_Al[o]     = l0;
    *(__nv_bfloat162*)&g_Al[o + 2] = l1;
}

// ---------------- kernel 4: Toeplitz conv via mma.sync ----------------
// CTA = (b, t-tile 128, k-half 128).  K dim = lag, chunks of 32.
// A[t][lag] = u[b, t0+t-lag0-lag]  materialized from SMEM u-window (hi/lo bf16).
// B[k][lag] = H[k][lag]  from pre-split g_Hh/g_Hl, cp.async double-buffered.
// 3 terms: Ah*Bh + Ah*Bl + Al*Bh.  Epilogue -> g_Ah/g_Al[m][k] hi/lo.
#define OF_AH 17408u
#define OF_AL 27648u
#define OF_B  37888u
#define CONV_SMEM 78848

__global__ void __launch_bounds__(256) k_tconv(float* dummy) {
    extern __shared__ char dsm[];
    float* usm = (float*)dsm;
    uint32_t sb = smem_u32(dsm);
    int id = blockIdx.x;
    int tt = 31 - (id >> 4);          // heavy tiles first
    int b = (id >> 1) & 7;
    int nh = id & 1;
    int t0 = tt << 7;
    int n0 = nh << 7;
    int tid = threadIdx.x, lane = tid & 31, wid = tid >> 5;
    int warpM = wid >> 2, warpN = wid & 3;
    int nch = tt * 4 + 4;

    // u window: usm[i] = u[b][i-127], zero for i<127
    int ulen = t0 + 255;
    for (int i = tid; i < ulen; i += 256) {
        int j = i - 127;
        usm[i] = (j >= 0) ? g_u[b * S_LEN + j] : 0.f;
    }

    // B prefetch lambda: Bh+Bl chunk -> buffer (c&1)
    int prow = tid >> 1;
    int ps2 = (tid & 1) << 1;
    auto prefetchB = [&](int c) {
        int lag0 = c << 5;
        const __nv_bfloat16* sh = g_Hh + (size_t)(n0 + prow) * S_LEN + lag0;
        const __nv_bfloat16* sl = g_Hl + (size_t)(n0 + prow) * S_LEN + lag0;
        uint32_t dh = sb + OF_B + (uint32_t)((c & 1) * 20480 + prow * 80);
        uint32_t dl = dh + 10240;
        CP_ASYNC16(dh + ps2 * 16, sh + ps2 * 8);
        CP_ASYNC16(dh + (ps2 + 1) * 16, sh + (ps2 + 1) * 8);
        CP_ASYNC16(dl + ps2 * 16, sl + ps2 * 8);
        CP_ASYNC16(dl + (ps2 + 1) * 16, sl + (ps2 + 1) * 8);
    };
    prefetchB(0);
    CP_COMMIT();
    __syncthreads();                  // usm ready

    float acc[4][4][4];
#pragma unroll
    for (int i = 0; i < 4; i++)
#pragma unroll
        for (int j = 0; j < 4; j++)
#pragma unroll
            for (int q = 0; q < 4; q++) acc[i][j][q] = 0.f;

    int arow = warpM * 64 + (lane & 15);
    int acolh = (lane >> 4) << 3;
    int brow = warpN * 32 + ((lane >> 4) << 3) + (lane & 7);
    int bcolh = ((lane >> 3) & 1) << 3;

    for (int c = 0; c < nch; c++) {
        int lag0 = c << 5;
        // materialize Toeplitz A tile (hi & lo), 128 x 32 halves, rows padded to 80B
        int base = t0 - lag0 + 127;
        for (int q = tid; q < 128 * 16; q += 256) {
            int t = q >> 4, lp = (q & 15) << 1;
            float v0 = usm[base + t - lp];
            float v1 = usm[base + t - lp - 1];
            __nv_bfloat162 hp, lp2;
            hp.x = __float2bfloat16(v0);
            hp.y = __float2bfloat16(v1);
            lp2.x = __float2bfloat16(v0 - __bfloat162float(hp.x));
            lp2.y = __float2bfloat16(v1 - __bfloat162float(hp.y));
            *(__nv_bfloat162*)(dsm + OF_AH + t * 80 + lp * 2) = hp;
            *(__nv_bfloat162*)(dsm + OF_AL + t * 80 + lp * 2) = lp2;
        }
        CP_WAIT0();
        __syncthreads();              // A stores + B(c) visible
        if (c + 1 < nch) { prefetchB(c + 1); CP_COMMIT(); }

        uint32_t sAh = sb + OF_AH, sAl = sb + OF_AL;
        uint32_t sBh = sb + OF_B + (uint32_t)((c & 1) * 20480);
        uint32_t sBl = sBh + 10240;
#pragma unroll
        for (int ks = 0; ks < 2; ks++) {
            int k0 = ks * 16;
            uint32_t ah[4][4], al[4][4], bh[4][2], bl[4][2];
#pragma unroll
            for (int mi = 0; mi < 4; mi++) {
                uint32_t off = (uint32_t)((arow + mi * 16) * 80 + (k0 + acolh) * 2);
                LDSM_X4(ah[mi][0], ah[mi][1], ah[mi][2], ah[mi][3], sAh + off);
                LDSM_X4(al[mi][0], al[mi][1], al[mi][2], al[mi][3], sAl + off);
            }
#pragma unroll
            for (int nj = 0; nj < 2; nj++) {
                uint32_t off = (uint32_t)((brow + nj * 16) * 80 + (k0 + bcolh) * 2);
                uint32_t r0, r1, r2, r3;
                LDSM_X4(r0, r1, r2, r3, sBh + off);
                bh[nj * 2][0] = r0;     bh[nj * 2][1] = r1;
                bh[nj * 2 + 1][0] = r2; bh[nj * 2 + 1][1] = r3;
                LDSM_X4(r0, r1, r2, r3, sBl + off);
                bl[nj * 2][0] = r0;     bl[nj * 2][1] = r1;
                bl[nj * 2 + 1][0] = r2; bl[nj * 2 + 1][1] = r3;
            }
#pragma unroll
            for (int mi = 0; mi < 4; mi++)
#pragma unroll
                for (int ni = 0; ni < 4; ni++) {
                    MMA16816(acc[mi][ni], ah[mi], bh[ni][0], bh[ni][1]);
                    MMA16816(acc[mi][ni], ah[mi], bl[ni][0], bl[ni][1]);
                    MMA16816(acc[mi][ni], al[mi], bh[ni][0], bh[ni][1]);
                }
        }
        __syncthreads();
    }

    // epilogue: split acc into bf16 hi/lo, write g_Ah/g_Al[m][k], k = conv dims [0,256)
    int erow = lane >> 2;
    int ecol = (lane & 3) << 1;
#pragma unroll
    for (int mi = 0; mi < 4; mi++) {
#pragma unroll
        for (int half = 0; half < 2; half++) {
            int m = b * S_LEN + t0 + warpM * 64 + mi * 16 + erow + half * 8;
#pragma unroll
            for (int ni = 0; ni < 4; ni++) {
                int k = n0 + warpN * 32 + ni * 8 + ecol;
                float v0 = acc[mi][ni][half * 2 + 0];
                float v1 = acc[mi][ni][half * 2 + 1];
                __nv_bfloat162 hp, lp;
                hp.x = __float2bfloat16(v0);
                hp.y = __float2bfloat16(v1);
                lp.x = __float2bfloat16(v0 - __bfloat162float(hp.x));
                lp.y = __float2bfloat16(v1 - __bfloat162float(hp.y));
                *(__nv_bfloat162*)&g_Ah[(size_t)m * KDIM + k] = hp;
                *(__nv_bfloat162*)&g_Al[(size_t)m * KDIM + k] = lp;
            }
        }
    }
}

// ---------------- kernel 5: mma.sync bf16 GEMM, h = relu(A @ W^T + b) ----------------
#define KC 32
#define ROWB 40
#define BUFB (128 * ROWB)
#define NCH 72

__global__ void __launch_bounds__(256) k_mgemm(const float* __restrict__ bias,
                                               float* __restrict__ out, long long out_size) {
    __shared__ __nv_bfloat16 smA[2][BUFB];
    __shared__ __nv_bfloat16 smB[2][BUFB];
    int tid = threadIdx.x, lane = tid & 31, wid = tid >> 5;
    int warpM = wid >> 2, warpN = wid & 3;
    int n0 = blockIdx.x * 128, R0 = blockIdx.y * 128;
    uint32_t aBase = smem_u32(smA), bBase = smem_u32(smB);

    float acc[4][4][4];
#pragma unroll
    for (int i = 0; i < 4; i++)
#pragma unroll
        for (int j = 0; j < 4; j++)
#pragma unroll
            for (int q = 0; q < 4; q++) acc[i][j][q] = 0.f;

    int prow = tid >> 2;
    int pseg = tid & 3;

    auto prefetch = [&](int c, int s) {
        int p = c / 24, kk = (c % 24) * KC;
        const __nv_bfloat16* As = (p < 2) ? g_Ah : g_Al;
        const __nv_bfloat16* Bs = (p == 1) ? g_Wl : g_Wh;
#pragma unroll
        for (int it = 0; it < 2; it++) {
            int row = prow + it * 64;
            uint32_t da = aBase + (uint32_t)(s * BUFB * 2 + row * 80 + pseg * 16);
            CP_ASYNC16(da, (const void*)(As + (size_t)(R0 + row) * KDIM + kk + pseg * 8));
            uint32_t db = bBase + (uint32_t)(s * BUFB * 2 + row * 80 + pseg * 16);
            CP_ASYNC16(db, (const void*)(Bs + (size_t)(n0 + row) * KDIM + kk + pseg * 8));
        }
    };

    prefetch(0, 0);
    CP_COMMIT();

    int arow = warpM * 64 + (lane & 15);
    int acolh = (lane >> 4) << 3;
    int brow = warpN * 32 + ((lane >> 4) << 3) + (lane & 7);
    int bcolh = ((lane >> 3) & 1) << 3;

    for (int c = 0; c < NCH; c++) {
        CP_WAIT0();
        __syncthreads();
        if (c + 1 < NCH) { prefetch(c + 1, (c + 1) & 1); CP_COMMIT(); }
        uint32_t sA = aBase + (uint32_t)((c & 1) * BUFB * 2);
        uint32_t sB = bBase + (uint32_t)((c & 1) * BUFB * 2);
#pragma unroll
        for (int ks = 0; ks < 2; ks++) {
            int k0 = ks * 16;
            uint32_t a[4][4], b[4][2];
#pragma unroll
            for (int mi = 0; mi < 4; mi++) {
                uint32_t ad = sA + (uint32_t)((arow + mi * 16) * 80 + (k0 + acolh) * 2);
                LDSM_X4(a[mi][0], a[mi][1], a[mi][2], a[mi][3], ad);
            }
#pragma unroll
            for (int nj = 0; nj < 2; nj++) {
                uint32_t bd = sB + (uint32_t)((brow + nj * 16) * 80 + (k0 + bcolh) * 2);
                uint32_t r0, r1, r2, r3;
                LDSM_X4(r0, r1, r2, r3, bd);
                b[nj * 2][0] = r0;     b[nj * 2][1] = r1;
                b[nj * 2 + 1][0] = r2; b[nj * 2 + 1][1] = r3;
            }
#pragma unroll
            for (int mi = 0; mi < 4; mi++)
#pragma unroll
                for (int ni = 0; ni < 4; ni++)
                    MMA16816(acc[mi][ni], a[mi], b[ni][0], b[ni][1]);
        }
        __syncthreads();
    }

    int erow = lane >> 2;
    int ecol = (lane & 3) << 1;
#pragma unroll
    for (int mi = 0; mi < 4; mi++) {
        int m0 = R0 + warpM * 64 + mi * 16 + erow;
#pragma unroll
        for (int ni = 0; ni < 4; ni++) {
            int n = n0 + warpN * 32 + ni * 8 + ecol;
            float b0 = bias[n], b1 = bias[n + 1];
            float2 v0, v1;
            v0.x = fmaxf(acc[mi][ni][0] + b0, 0.f);
            v0.y = fmaxf(acc[mi][ni][1] + b1, 0.f);
            v1.x = fmaxf(acc[mi][ni][2] + b0, 0.f);
            v1.y = fmaxf(acc[mi][ni][3] + b1, 0.f);
            int m1 = m0 + 8;
            *(float2*)&out[(size_t)m0 * N_HID + n] = v0;
            *(float2*)&out[(size_t)m1 * N_HID + n] = v1;
            if ((m0 & (S_LEN - 1)) == (S_LEN - 1)) {
                long long ti = (long long)M_ROWS * N_HID + (long long)(m0 >> 12) * N_HID + n;
                if (ti + 1 < out_size) *(float2*)&out[ti] = v0;
            }
            if ((m1 & (S_LEN - 1)) == (S_LEN - 1)) {
                long long ti = (long long)M_ROWS * N_HID + (long long)(m1 >> 12) * N_HID + n;
                if (ti + 1 < out_size) *(float2*)&out[ti] = v1;
            }
        }
    }
}

// ---------------- launch ----------------
extern "C" void kernel_launch(void* const* d_in, const int* in_sizes, int n_in,
                              void* d_out, int out_size) {
    const float *x = nullptr, *Wuw = nullptr, *Wub = nullptr, *Whw = nullptr,
                *Whb = nullptr, *H = nullptr;
    for (int i = 0; i < n_in; i++) {
        switch (in_sizes[i]) {
            case 16777216: x   = (const float*)d_in[i]; break;
            case 512:      Wuw = (const float*)d_in[i]; break;
            case 1:        Wub = (const float*)d_in[i]; break;
            case 786432:   Whw = (const float*)d_in[i]; break;
            case 1024:     Whb = (const float*)d_in[i]; break;
            case 1048576:  H   = (const float*)d_in[i]; break;
        }
    }
    float* out = (float*)d_out;

    static int s_attr_done = 0;
    if (!s_attr_done) {
        cudaFuncSetAttribute(k_tconv, cudaFuncAttributeMaxDynamicSharedMemorySize, CONV_SMEM);
        s_attr_done = 1;
    }

    __nv_bfloat16 *dWh, *dWl, *dHh, *dHl;
    cudaGetSymbolAddress((void**)&dWh, g_Wh);
    cudaGetSymbolAddress((void**)&dWl, g_Wl);
    cudaGetSymbolAddress((void**)&dHh, g_Hh);
    cudaGetSymbolAddress((void**)&dHl, g_Hl);

    k_u     <<<M_ROWS / 8, 256>>>(x, Wuw, Wub);
    k_cvt_x <<<M_ROWS * D_IN / 4 / 256, 256>>>(x);
    k_split <<<N_HID * KDIM / 4 / 256, 256>>>(Whw, dWh, dWl);
    k_split <<<K_MEM * S_LEN / 4 / 256, 256>>>(H, dHh, dHl);
    k_tconv <<<512, 256, CONV_SMEM>>>(nullptr);
    k_mgemm <<<dim3(N_HID / 128, M_ROWS / 128), 256>>>(Whb, out, (long long)out_size);
}

// round 7
// speedup vs baseline: 2.0927x; 1.0545x over previous
#include <cuda_runtime.h>
#include <cuda_bf16.h>
#include <cstdint>
#include <cstddef>

#define S_LEN 4096
#define D_IN  512
#define K_MEM 256
#define N_HID 1024
#define BATCH 8
#define KDIM  (K_MEM + D_IN)          // 768
#define M_ROWS (BATCH * S_LEN)        // 32768

// ---------------- scratch (static device memory; no allocations) ----------------
__device__ float g_u[M_ROWS];
__device__ __nv_bfloat16 g_Ah[(size_t)M_ROWS * KDIM];    // A hi, [m][k]
__device__ __nv_bfloat16 g_Al[(size_t)M_ROWS * KDIM];    // A lo
__device__ __nv_bfloat16 g_Wh[(size_t)N_HID * KDIM];     // W hi, [n][k]
__device__ __nv_bfloat16 g_Wl[(size_t)N_HID * KDIM];     // W lo
__device__ __nv_bfloat16 g_Hh[(size_t)K_MEM * S_LEN];    // H hi, [k][lag]
__device__ __nv_bfloat16 g_Hl[(size_t)K_MEM * S_LEN];    // H lo

// ---------------- helpers ----------------
__device__ __forceinline__ uint32_t smem_u32(const void* p) {
    uint32_t a;
    asm("{ .reg .u64 t; cvta.to.shared.u64 t, %1; cvt.u32.u64 %0, t; }" : "=r"(a) : "l"(p));
    return a;
}
#define CP_ASYNC16(dst, src) \
    asm volatile("cp.async.cg.shared.global [%0], [%1], 16;" :: "r"(dst), "l"(src) : "memory")
#define CP_COMMIT()  asm volatile("cp.async.commit_group;" ::: "memory")
#define CP_WAIT0()   asm volatile("cp.async.wait_group 0;" ::: "memory")
#define CP_WAIT1()   asm volatile("cp.async.wait_group 1;" ::: "memory")
#define LDSM_X4(r0, r1, r2, r3, addr) \
    asm volatile("ldmatrix.sync.aligned.m8n8.x4.shared.b16 {%0,%1,%2,%3}, [%4];" \
                 : "=r"(r0), "=r"(r1), "=r"(r2), "=r"(r3) : "r"(addr))
#define MMA16816(d, a, b0, b1) \
    asm volatile("mma.sync.aligned.m16n8k16.row.col.f32.bf16.bf16.f32 " \
                 "{%0,%1,%2,%3}, {%4,%5,%6,%7}, {%8,%9}, {%0,%1,%2,%3};" \
                 : "+f"((d)[0]), "+f"((d)[1]), "+f"((d)[2]), "+f"((d)[3]) \
                 : "r"((a)[0]), "r"((a)[1]), "r"((a)[2]), "r"((a)[3]), "r"(b0), "r"(b1))

// ---------------- kernel 1: u = relu(x @ w + b) ----------------
__global__ void k_u(const float* __restrict__ x, const float* __restrict__ w,
                    const float* __restrict__ bias) {
    int R = blockIdx.x * 8 + (threadIdx.x >> 5);
    int lane = threadIdx.x & 31;
    const float4* xr = (const float4*)(x + (size_t)R * D_IN);
    const float4* wv = (const float4*)w;
    float s = 0.f;
#pragma unroll
    for (int j = 0; j < 4; j++) {
        float4 a = xr[lane + 32 * j];
        float4 b = wv[lane + 32 * j];
        s += a.x * b.x + a.y * b.y + a.z * b.z + a.w * b.w;
    }
#pragma unroll
    for (int o = 16; o; o >>= 1) s += __shfl_xor_sync(0xffffffffu, s, o);
    if (lane == 0) g_u[R] = fmaxf(s + bias[0], 0.f);
}

// ---------------- kernel 2: generic fp32 -> bf16 hi/lo split ----------------
__global__ void k_split(const float* __restrict__ src, __nv_bfloat16* __restrict__ dh,
                        __nv_bfloat16* __restrict__ dl) {
    size_t o = ((size_t)blockIdx.x * 256 + threadIdx.x) * 4;
    float4 v = *(const float4*)(src + o);
    __nv_bfloat162 h0 = __floats2bfloat162_rn(v.x, v.y);
    __nv_bfloat162 h1 = __floats2bfloat162_rn(v.z, v.w);
    *(__nv_bfloat162*)&dh[o]     = h0;
    *(__nv_bfloat162*)&dh[o + 2] = h1;
    __nv_bfloat162 l0 = __floats2bfloat162_rn(v.x - __bfloat162float(h0.x),
                                              v.y - __bfloat162float(h0.y));
    __nv_bfloat162 l1 = __floats2bfloat162_rn(v.z - __bfloat162float(h1.x),
                                              v.w - __bfloat162float(h1.y));
    *(__nv_bfloat162*)&dl[o]     = l0;
    *(__nv_bfloat162*)&dl[o + 2] = l1;
}

// ---------------- kernel 3: stream-convert x -> A hi/lo [m][256..768) ----------------
__global__ void k_cvt_x(const float* __restrict__ x) {
    int g = blockIdx.x * 256 + threadIdx.x;
    int base = g * 4;
    int m = base >> 9, d = base & 511;
    float4 v = *(const float4*)(x + (size_t)m * D_IN + d);
    size_t o = (size_t)m * KDIM + K_MEM + d;
    __nv_bfloat162 h0 = __floats2bfloat162_rn(v.x, v.y);
    __nv_bfloat162 h1 = __floats2bfloat162_rn(v.z, v.w);
    *(__nv_bfloat162*)&g_Ah[o]     = h0;
    *(__nv_bfloat162*)&g_Ah[o + 2] = h1;
    __nv_bfloat162 l0 = __floats2bfloat162_rn(v.x - __bfloat162float(h0.x),
                                              v.y - __bfloat162float(h0.y));
    __nv_bfloat162 l1 = __floats2bfloat162_rn(v.z - __bfloat162float(h1.x),
                                              v.w - __bfloat162float(h1.y));
    *(__nv_bfloat162*)&g_Al[o]     = l0;
    *(__nv_bfloat162*)&g_Al[o + 2] = l1;
}

// ---------------- kernel 4: Toeplitz conv via mma.sync (unchanged, verified) ----------------
#define OF_AH 17408u
#define OF_AL 27648u
#define OF_B  37888u
#define CONV_SMEM 78848

__global__ void __launch_bounds__(256) k_tconv(float* dummy) {
    extern __shared__ char dsm[];
    float* usm = (float*)dsm;
    uint32_t sb = smem_u32(dsm);
    int id = blockIdx.x;
    int tt = 31 - (id >> 4);
    int b = (id >> 1) & 7;
    int nh = id & 1;
    int t0 = tt << 7;
    int n0 = nh << 7;
    int tid = threadIdx.x, lane = tid & 31, wid = tid >> 5;
    int warpM = wid >> 2, warpN = wid & 3;
    int nch = tt * 4 + 4;

    int ulen = t0 + 255;
    for (int i = tid; i < ulen; i += 256) {
        int j = i - 127;
        usm[i] = (j >= 0) ? g_u[b * S_LEN + j] : 0.f;
    }

    int prow = tid >> 1;
    int ps2 = (tid & 1) << 1;
    auto prefetchB = [&](int c) {
        int lag0 = c << 5;
        const __nv_bfloat16* sh = g_Hh + (size_t)(n0 + prow) * S_LEN + lag0;
        const __nv_bfloat16* sl = g_Hl + (size_t)(n0 + prow) * S_LEN + lag0;
        uint32_t dh = sb + OF_B + (uint32_t)((c & 1) * 20480 + prow * 80);
        uint32_t dl = dh + 10240;
        CP_ASYNC16(dh + ps2 * 16, sh + ps2 * 8);
        CP_ASYNC16(dh + (ps2 + 1) * 16, sh + (ps2 + 1) * 8);
        CP_ASYNC16(dl + ps2 * 16, sl + ps2 * 8);
        CP_ASYNC16(dl + (ps2 + 1) * 16, sl + (ps2 + 1) * 8);
    };
    prefetchB(0);
    CP_COMMIT();
    __syncthreads();

    float acc[4][4][4];
#pragma unroll
    for (int i = 0; i < 4; i++)
#pragma unroll
        for (int j = 0; j < 4; j++)
#pragma unroll
            for (int q = 0; q < 4; q++) acc[i][j][q] = 0.f;

    int arow = warpM * 64 + (lane & 15);
    int acolh = (lane >> 4) << 3;
    int brow = warpN * 32 + ((lane >> 4) << 3) + (lane & 7);
    int bcolh = ((lane >> 3) & 1) << 3;

    for (int c = 0; c < nch; c++) {
        int lag0 = c << 5;
        int base = t0 - lag0 + 127;
        for (int q = tid; q < 128 * 16; q += 256) {
            int t = q >> 4, lp = (q & 15) << 1;
            float v0 = usm[base + t - lp];
            float v1 = usm[base + t - lp - 1];
            __nv_bfloat162 hp, lp2;
            hp.x = __float2bfloat16(v0);
            hp.y = __float2bfloat16(v1);
            lp2.x = __float2bfloat16(v0 - __bfloat162float(hp.x));
            lp2.y = __float2bfloat16(v1 - __bfloat162float(hp.y));
            *(__nv_bfloat162*)(dsm + OF_AH + t * 80 + lp * 2) = hp;
            *(__nv_bfloat162*)(dsm + OF_AL + t * 80 + lp * 2) = lp2;
        }
        CP_WAIT0();
        __syncthreads();
        if (c + 1 < nch) { prefetchB(c + 1); CP_COMMIT(); }

        uint32_t sAh = sb + OF_AH, sAl = sb + OF_AL;
        uint32_t sBh = sb + OF_B + (uint32_t)((c & 1) * 20480);
        uint32_t sBl = sBh + 10240;
#pragma unroll
        for (int ks = 0; ks < 2; ks++) {
            int k0 = ks * 16;
            uint32_t ah[4][4], al[4][4], bh[4][2], bl[4][2];
#pragma unroll
            for (int mi = 0; mi < 4; mi++) {
                uint32_t off = (uint32_t)((arow + mi * 16) * 80 + (k0 + acolh) * 2);
                LDSM_X4(ah[mi][0], ah[mi][1], ah[mi][2], ah[mi][3], sAh + off);
                LDSM_X4(al[mi][0], al[mi][1], al[mi][2], al[mi][3], sAl + off);
            }
#pragma unroll
            for (int nj = 0; nj < 2; nj++) {
                uint32_t off = (uint32_t)((brow + nj * 16) * 80 + (k0 + bcolh) * 2);
                uint32_t r0, r1, r2, r3;
                LDSM_X4(r0, r1, r2, r3, sBh + off);
                bh[nj * 2][0] = r0;     bh[nj * 2][1] = r1;
                bh[nj * 2 + 1][0] = r2; bh[nj * 2 + 1][1] = r3;
                LDSM_X4(r0, r1, r2, r3, sBl + off);
                bl[nj * 2][0] = r0;     bl[nj * 2][1] = r1;
                bl[nj * 2 + 1][0] = r2; bl[nj * 2 + 1][1] = r3;
            }
#pragma unroll
            for (int mi = 0; mi < 4; mi++)
#pragma unroll
                for (int ni = 0; ni < 4; ni++) {
                    MMA16816(acc[mi][ni], ah[mi], bh[ni][0], bh[ni][1]);
                    MMA16816(acc[mi][ni], ah[mi], bl[ni][0], bl[ni][1]);
                    MMA16816(acc[mi][ni], al[mi], bh[ni][0], bh[ni][1]);
                }
        }
        __syncthreads();
    }

    int erow = lane >> 2;
    int ecol = (lane & 3) << 1;
#pragma unroll
    for (int mi = 0; mi < 4; mi++) {
#pragma unroll
        for (int half = 0; half < 2; half++) {
            int m = b * S_LEN + t0 + warpM * 64 + mi * 16 + erow + half * 8;
#pragma unroll
            for (int ni = 0; ni < 4; ni++) {
                int k = n0 + warpN * 32 + ni * 8 + ecol;
                float v0 = acc[mi][ni][half * 2 + 0];
                float v1 = acc[mi][ni][half * 2 + 1];
                __nv_bfloat162 hp, lp;
                hp.x = __float2bfloat16(v0);
                hp.y = __float2bfloat16(v1);
                lp.x = __float2bfloat16(v0 - __bfloat162float(hp.x));
                lp.y = __float2bfloat16(v1 - __bfloat162float(hp.y));
                *(__nv_bfloat162*)&g_Ah[(size_t)m * KDIM + k] = hp;
                *(__nv_bfloat162*)&g_Al[(size_t)m * KDIM + k] = lp;
            }
        }
    }
}

// ---------------- kernel 5: fused 3-term bf16 GEMM, h = relu(A @ W^T + b) ----------------
// CTA tile M=128 x N=256, 512 threads (warp tile 32x64).  Single K pass (24 chunks
// of 32); per chunk load Ah,Al,Wh,Wl and issue Ah*Wh + Ah*Wl + Al*Wh.
// 3-stage cp.async pipeline, wait_group 1.  Rows padded to 80B.
#define STG_B 61440u                   // bytes per stage: Ah 10240 + Al 10240 + Wh 20480 + Wl 20480
#define GSMEM (3 * STG_B)
#define OFF_AL 10240u
#define OFF_WH 20480u
#define OFF_WL 40960u

__global__ void __launch_bounds__(512) k_mgemm(const float* __restrict__ bias,
                                               float* __restrict__ out, long long out_size) {
    extern __shared__ char dsm[];
    uint32_t sb = smem_u32(dsm);
    int tid = threadIdx.x, lane = tid & 31, wid = tid >> 5;
    int warpM = wid & 3, warpN = wid >> 2;
    int n0 = blockIdx.x * 256, R0 = blockIdx.y * 128;

    float acc[2][8][4];
#pragma unroll
    for (int i = 0; i < 2; i++)
#pragma unroll
        for (int j = 0; j < 8; j++)
#pragma unroll
            for (int q = 0; q < 4; q++) acc[i][j][q] = 0.f;

    int arow_l = tid >> 2, aseg = tid & 3;          // A: 128 rows x 4 segs
    int wrow_l = tid >> 1, wseg = (tid & 1) << 1;   // W: 256 rows x 2 segs each

    auto prefetch = [&](int c, int s) {
        int kk = c * 32;
        uint32_t st = sb + (uint32_t)s * STG_B;
        CP_ASYNC16(st + (uint32_t)(arow_l * 80 + aseg * 16),
                   g_Ah + (size_t)(R0 + arow_l) * KDIM + kk + aseg * 8);
        CP_ASYNC16(st + OFF_AL + (uint32_t)(arow_l * 80 + aseg * 16),
                   g_Al + (size_t)(R0 + arow_l) * KDIM + kk + aseg * 8);
        const __nv_bfloat16* wh = g_Wh + (size_t)(n0 + wrow_l) * KDIM + kk + wseg * 8;
        const __nv_bfloat16* wl = g_Wl + (size_t)(n0 + wrow_l) * KDIM + kk + wseg * 8;
        uint32_t dwh = st + OFF_WH + (uint32_t)(wrow_l * 80 + wseg * 16);
        uint32_t dwl = st + OFF_WL + (uint32_t)(wrow_l * 80 + wseg * 16);
        CP_ASYNC16(dwh, wh);
        CP_ASYNC16(dwh + 16, wh + 8);
        CP_ASYNC16(dwl, wl);
        CP_ASYNC16(dwl + 16, wl + 8);
    };

    prefetch(0, 0); CP_COMMIT();
    prefetch(1, 1); CP_COMMIT();

    int arow = warpM * 32 + (lane & 15);
    int acolh = (lane >> 4) << 3;
    int brow_b = warpN * 64 + ((lane >> 4) << 3) + (lane & 7);
    int bcolh = ((lane >> 3) & 1) << 3;

    for (int c = 0; c < 24; c++) {
        CP_WAIT1();
        __syncthreads();
        if (c + 2 < 24) { prefetch(c + 2, (c + 2) % 3); CP_COMMIT(); }
        uint32_t st = sb + (uint32_t)(c % 3) * STG_B;
#pragma unroll
        for (int ks = 0; ks < 2; ks++) {
            int k0 = ks * 16;
            uint32_t ah[2][4], al[2][4], bh[8][2], bl[8][2];
#pragma unroll
            for (int mi = 0; mi < 2; mi++) {
                uint32_t off = (uint32_t)((arow + mi * 16) * 80 + (k0 + acolh) * 2);
                LDSM_X4(ah[mi][0], ah[mi][1], ah[mi][2], ah[mi][3], st + off);
                LDSM_X4(al[mi][0], al[mi][1], al[mi][2], al[mi][3], st + OFF_AL + off);
            }
#pragma unroll
            for (int nj = 0; nj < 4; nj++) {
                uint32_t off = (uint32_t)((brow_b + nj * 16) * 80 + (k0 + bcolh) * 2);
                uint32_t r0, r1, r2, r3;
                LDSM_X4(r0, r1, r2, r3, st + OFF_WH + off);
                bh[nj * 2][0] = r0;     bh[nj * 2][1] = r1;
                bh[nj * 2 + 1][0] = r2; bh[nj * 2 + 1][1] = r3;
                LDSM_X4(r0, r1, r2, r3, st + OFF_WL + off);
                bl[nj * 2][0] = r0;     bl[nj * 2][1] = r1;
                bl[nj * 2 + 1][0] = r2; bl[nj * 2 + 1][1] = r3;
            }
#pragma unroll
            for (int mi = 0; mi < 2; mi++)
#pragma unroll
                for (int ni = 0; ni < 8; ni++) {
                    MMA16816(acc[mi][ni], ah[mi], bh[ni][0], bh[ni][1]);
                    MMA16816(acc[mi][ni], ah[mi], bl[ni][0], bl[ni][1]);
                    MMA16816(acc[mi][ni], al[mi], bh[ni][0], bh[ni][1]);
                }
        }
        __syncthreads();
    }

    int erow = lane >> 2;
    int ecol = (lane & 3) << 1;
#pragma unroll
    for (int mi = 0; mi < 2; mi++) {
        int m0 = R0 + warpM * 32 + mi * 16 + erow;
#pragma unroll
        for (int ni = 0; ni < 8; ni++) {
            int n = n0 + warpN * 64 + ni * 8 + ecol;
            float b0 = bias[n], b1 = bias[n + 1];
            float2 v0, v1;
            v0.x = fmaxf(acc[mi][ni][0] + b0, 0.f);
            v0.y = fmaxf(acc[mi][ni][1] + b1, 0.f);
            v1.x = fmaxf(acc[mi][ni][2] + b0, 0.f);
            v1.y = fmaxf(acc[mi][ni][3] + b1, 0.f);
            int m1 = m0 + 8;
            *(float2*)&out[(size_t)m0 * N_HID + n] = v0;
            *(float2*)&out[(size_t)m1 * N_HID + n] = v1;
            if ((m0 & (S_LEN - 1)) == (S_LEN - 1)) {
                long long ti = (long long)M_ROWS * N_HID + (long long)(m0 >> 12) * N_HID + n;
                if (ti + 1 < out_size) *(float2*)&out[ti] = v0;
            }
            if ((m1 & (S_LEN - 1)) == (S_LEN - 1)) {
                long long ti = (long long)M_ROWS * N_HID + (long long)(m1 >> 12) * N_HID + n;
                if (ti + 1 < out_size) *(float2*)&out[ti] = v1;
            }
        }
    }
}

// ---------------- launch ----------------
extern "C" void kernel_launch(void* const* d_in, const int* in_sizes, int n_in,
                              void* d_out, int out_size) {
    const float *x = nullptr, *Wuw = nullptr, *Wub = nullptr, *Whw = nullptr,
                *Whb = nullptr, *H = nullptr;
    for (int i = 0; i < n_in; i++) {
        switch (in_sizes[i]) {
            case 16777216: x   = (const float*)d_in[i]; break;
            case 512:      Wuw = (const float*)d_in[i]; break;
            case 1:        Wub = (const float*)d_in[i]; break;
            case 786432:   Whw = (const float*)d_in[i]; break;
            case 1024:     Whb = (const float*)d_in[i]; break;
            case 1048576:  H   = (const float*)d_in[i]; break;
        }
    }
    float* out = (float*)d_out;

    static int s_attr_done = 0;
    if (!s_attr_done) {
        cudaFuncSetAttribute(k_tconv, cudaFuncAttributeMaxDynamicSharedMemorySize, CONV_SMEM);
        cudaFuncSetAttribute(k_mgemm, cudaFuncAttributeMaxDynamicSharedMemorySize, GSMEM);
        s_attr_done = 1;
    }

    __nv_bfloat16 *dWh, *dWl, *dHh, *dHl;
    cudaGetSymbolAddress((void**)&dWh, g_Wh);
    cudaGetSymbolAddress((void**)&dWl, g_Wl);
    cudaGetSymbolAddress((void**)&dHh, g_Hh);
    cudaGetSymbolAddress((void**)&dHl, g_Hl);

    k_u     <<<M_ROWS / 8, 256>>>(x, Wuw, Wub);
    k_cvt_x <<<M_ROWS * D_IN / 4 / 256, 256>>>(x);
    k_split <<<N_HID * KDIM / 4 / 256, 256>>>(Whw, dWh, dWl);
    k_split <<<K_MEM * S_LEN / 4 / 256, 256>>>(H, dHh, dHl);
    k_tconv <<<512, 256, CONV_SMEM>>>(nullptr);
    k_mgemm <<<dim3(N_HID / 256, M_ROWS / 128), 512, GSMEM>>>(Whb, out, (long long)out_size);
}

// round 11
// speedup vs baseline: 3.0483x; 1.4567x over previous
#include <cuda_runtime.h>
#include <cuda_fp16.h>
#include <cstdint>
#include <cstddef>

#define S_LEN 4096
#define D_IN  512
#define K_MEM 256
#define N_HID 1024
#define BATCH 8
#define KDIM  (K_MEM + D_IN)          // 768
#define M_ROWS (BATCH * S_LEN)        // 32768

// ---------------- scratch (static device memory; no allocations) ----------------
__device__ float g_u[M_ROWS];
__device__ __half g_Ah[(size_t)M_ROWS * KDIM];    // A hi (fp16), [m][k]
__device__ __half g_Al[(size_t)M_ROWS * KDIM];    // A lo (fp16)
__device__ __half g_W[(size_t)N_HID * KDIM];      // W fp16, [n][k]
__device__ __half g_H[(size_t)K_MEM * S_LEN];     // H fp16, [k][lag]

// ---------------- helpers ----------------
__device__ __forceinline__ uint32_t smem_u32(const void* p) {
    uint32_t a;
    asm("{ .reg .u64 t; cvta.to.shared.u64 t, %1; cvt.u32.u64 %0, t; }" : "=r"(a) : "l"(p));
    return a;
}
#define CP_ASYNC16(dst, src) \
    asm volatile("cp.async.cg.shared.global [%0], [%1], 16;" :: "r"(dst), "l"(src) : "memory")
#define CP_COMMIT()  asm volatile("cp.async.commit_group;" ::: "memory")
#define CP_WAIT0()   asm volatile("cp.async.wait_group 0;" ::: "memory")
#define CP_WAIT1()   asm volatile("cp.async.wait_group 1;" ::: "memory")
#define LDSM_X4(r0, r1, r2, r3, addr) \
    asm volatile("ldmatrix.sync.aligned.m8n8.x4.shared.b16 {%0,%1,%2,%3}, [%4];" \
                 : "=r"(r0), "=r"(r1), "=r"(r2), "=r"(r3) : "r"(addr))
#define MMA16816(d, a, b0, b1) \
    asm volatile("mma.sync.aligned.m16n8k16.row.col.f32.f16.f16.f32 " \
                 "{%0,%1,%2,%3}, {%4,%5,%6,%7}, {%8,%9}, {%0,%1,%2,%3};" \
                 : "+f"((d)[0]), "+f"((d)[1]), "+f"((d)[2]), "+f"((d)[3]) \
                 : "r"((a)[0]), "r"((a)[1]), "r"((a)[2]), "r"((a)[3]), "r"(b0), "r"(b1))

// ---------------- kernel 1: u = relu(x @ w + b) ----------------
__global__ void k_u(const float* __restrict__ x, const float* __restrict__ w,
                    const float* __restrict__ bias) {
    int R = blockIdx.x * 8 + (threadIdx.x >> 5);
    int lane = threadIdx.x & 31;
    const float4* xr = (const float4*)(x + (size_t)R * D_IN);
    const float4* wv = (const float4*)w;
    float s = 0.f;
#pragma unroll
    for (int j = 0; j < 4; j++) {
        float4 a = xr[lane + 32 * j];
        float4 b = wv[lane + 32 * j];
        s += a.x * b.x + a.y * b.y + a.z * b.z + a.w * b.w;
    }
#pragma unroll
    for (int o = 16; o; o >>= 1) s += __shfl_xor_sync(0xffffffffu, s, o);
    if (lane == 0) g_u[R] = fmaxf(s + bias[0], 0.f);
}

// ---------------- kernel 2: fp32 -> fp16 round (single) ----------------
__global__ void k_round(const float* __restrict__ src, __half* __restrict__ dst) {
    size_t o = ((size_t)blockIdx.x * 256 + threadIdx.x) * 4;
    float4 v = *(const float4*)(src + o);
    __half2 h0 = __floats2half2_rn(v.x, v.y);
    __half2 h1 = __floats2half2_rn(v.z, v.w);
    *(__half2*)&dst[o]     = h0;
    *(__half2*)&dst[o + 2] = h1;
}

// ---------------- kernel 3: stream-convert x -> A hi/lo fp16 [m][256..768) ----------------
__global__ void k_cvt_x(const float* __restrict__ x) {
    int g = blockIdx.x * 256 + threadIdx.x;
    int base = g * 4;
    int m = base >> 9, d = base & 511;
    float4 v = *(const float4*)(x + (size_t)m * D_IN + d);
    size_t o = (size_t)m * KDIM + K_MEM + d;
    __half2 h0 = __floats2half2_rn(v.x, v.y);
    __half2 h1 = __floats2half2_rn(v.z, v.w);
    *(__half2*)&g_Ah[o]     = h0;
    *(__half2*)&g_Ah[o + 2] = h1;
    __half2 l0 = __floats2half2_rn(v.x - __half2float(h0.x), v.y - __half2float(h0.y));
    __half2 l1 = __floats2half2_rn(v.z - __half2float(h1.x), v.w - __half2float(h1.y));
    *(__half2*)&g_Al[o]     = l0;
    *(__half2*)&g_Al[o + 2] = l1;
}

// ---------------- kernel 4: Toeplitz conv via mma.sync (fp16, 2-term) ----------------
// CTA = (b, t-tile 128, k-half 128).  A[t][lag] = u[t0+t-lag0-lag] split fp16 hi/lo,
// B[k][lag] = H (single fp16).  acc = uh*H + ul*H.
#define OF_AH 17408u
#define OF_AL 27648u
#define OF_B  37888u
#define CONV_SMEM 58368

__global__ void __launch_bounds__(256) k_tconv(float* dummy) {
    extern __shared__ char dsm[];
    float* usm = (float*)dsm;
    uint32_t sb = smem_u32(dsm);
    int id = blockIdx.x;
    int tt = 31 - (id >> 4);          // heavy tiles first
    int b = (id >> 1) & 7;
    int nh = id & 1;
    int t0 = tt << 7;
    int n0 = nh << 7;
    int tid = threadIdx.x, lane = tid & 31, wid = tid >> 5;
    int warpM = wid >> 2, warpN = wid & 3;
    int nch = tt * 4 + 4;

    int ulen = t0 + 255;
    for (int i = tid; i < ulen; i += 256) {
        int j = i - 127;
        usm[i] = (j >= 0) ? g_u[b * S_LEN + j] : 0.f;
    }

    int prow = tid >> 1;
    int ps2 = (tid & 1) << 1;
    auto prefetchB = [&](int c) {
        int lag0 = c << 5;
        const __half* sh = g_H + (size_t)(n0 + prow) * S_LEN + lag0;
        uint32_t dh = sb + OF_B + (uint32_t)((c & 1) * 10240 + prow * 80);
        CP_ASYNC16(dh + ps2 * 16, sh + ps2 * 8);
        CP_ASYNC16(dh + (ps2 + 1) * 16, sh + (ps2 + 1) * 8);
    };
    prefetchB(0);
    CP_COMMIT();
    __syncthreads();

    float acc[4][4][4];
#pragma unroll
    for (int i = 0; i < 4; i++)
#pragma unroll
        for (int j = 0; j < 4; j++)
#pragma unroll
            for (int q = 0; q < 4; q++) acc[i][j][q] = 0.f;

    int arow = warpM * 64 + (lane & 15);
    int acolh = (lane >> 4) << 3;
    int brow = warpN * 32 + ((lane >> 4) << 3) + (lane & 7);
    int bcolh = ((lane >> 3) & 1) << 3;

    for (int c = 0; c < nch; c++) {
        int lag0 = c << 5;
        int base = t0 - lag0 + 127;
        for (int q = tid; q < 128 * 16; q += 256) {
            int t = q >> 4, lp = (q & 15) << 1;
            float v0 = usm[base + t - lp];
            float v1 = usm[base + t - lp - 1];
            __half2 hp, lo;
            hp.x = __float2half_rn(v0);
            hp.y = __float2half_rn(v1);
            lo.x = __float2half_rn(v0 - __half2float(hp.x));
            lo.y = __float2half_rn(v1 - __half2float(hp.y));
            *(__half2*)(dsm + OF_AH + t * 80 + lp * 2) = hp;
            *(__half2*)(dsm + OF_AL + t * 80 + lp * 2) = lo;
        }
        CP_WAIT0();
        __syncthreads();
        if (c + 1 < nch) { prefetchB(c + 1); CP_COMMIT(); }

        uint32_t sAh = sb + OF_AH, sAl = sb + OF_AL;
        uint32_t sBh = sb + OF_B + (uint32_t)((c & 1) * 10240);
#pragma unroll
        for (int ks = 0; ks < 2; ks++) {
            int k0 = ks * 16;
            uint32_t ah[4][4], al[4][4], bh[4][2];
#pragma unroll
            for (int mi = 0; mi < 4; mi++) {
                uint32_t off = (uint32_t)((arow + mi * 16) * 80 + (k0 + acolh) * 2);
                LDSM_X4(ah[mi][0], ah[mi][1], ah[mi][2], ah[mi][3], sAh + off);
                LDSM_X4(al[mi][0], al[mi][1], al[mi][2], al[mi][3], sAl + off);
            }
#pragma unroll
            for (int nj = 0; nj < 2; nj++) {
                uint32_t off = (uint32_t)((brow + nj * 16) * 80 + (k0 + bcolh) * 2);
                uint32_t r0, r1, r2, r3;
                LDSM_X4(r0, r1, r2, r3, sBh + off);
                bh[nj * 2][0] = r0;     bh[nj * 2][1] = r1;
                bh[nj * 2 + 1][0] = r2; bh[nj * 2 + 1][1] = r3;
            }
#pragma unroll
            for (int mi = 0; mi < 4; mi++)
#pragma unroll
                for (int ni = 0; ni < 4; ni++) {
                    MMA16816(acc[mi][ni], ah[mi], bh[ni][0], bh[ni][1]);
                    MMA16816(acc[mi][ni], al[mi], bh[ni][0], bh[ni][1]);
                }
        }
        __syncthreads();
    }

    // epilogue: split acc into fp16 hi/lo -> g_Ah/g_Al[m][k], k in [0,256)
    int erow = lane >> 2;
    int ecol = (lane & 3) << 1;
#pragma unroll
    for (int mi = 0; mi < 4; mi++) {
#pragma unroll
        for (int half = 0; half < 2; half++) {
            int m = b * S_LEN + t0 + warpM * 64 + mi * 16 + erow + half * 8;
#pragma unroll
            for (int ni = 0; ni < 4; ni++) {
                int k = n0 + warpN * 32 + ni * 8 + ecol;
                float v0 = acc[mi][ni][half * 2 + 0];
                float v1 = acc[mi][ni][half * 2 + 1];
                __half2 hp, lo;
                hp.x = __float2half_rn(v0);
                hp.y = __float2half_rn(v1);
                lo.x = __float2half_rn(v0 - __half2float(hp.x));
                lo.y = __float2half_rn(v1 - __half2float(hp.y));
                *(__half2*)&g_Ah[(size_t)m * KDIM + k] = hp;
                *(__half2*)&g_Al[(size_t)m * KDIM + k] = lo;
            }
        }
    }
}

// ---------------- kernel 5: fused 2-term fp16 GEMM, h = relu(A @ W^T + b) ----------------
// CTA tile M=128 x N=256, 512 threads.  24 K-chunks of 32; per chunk load Ah,Al,W,
// acc = Ah*W + Al*W.  3-stage cp.async, wait_group 1.  Rows padded to 80B.
#define STG_B 40960u                   // Ah 10240 + Al 10240 + W 20480
#define GSMEM (3 * STG_B)
#define OFF_AL 10240u
#define OFF_W  20480u

__global__ void __launch_bounds__(512) k_mgemm(const float* __restrict__ bias,
                                               float* __restrict__ out, long long out_size) {
    extern __shared__ char dsm[];
    uint32_t sb = smem_u32(dsm);
    int tid = threadIdx.x, lane = tid & 31, wid = tid >> 5;
    int warpM = wid & 3, warpN = wid >> 2;
    int n0 = blockIdx.x * 256, R0 = blockIdx.y * 128;

    float acc[2][8][4];
#pragma unroll
    for (int i = 0; i < 2; i++)
#pragma unroll
        for (int j = 0; j < 8; j++)
#pragma unroll
            for (int q = 0; q < 4; q++) acc[i][j][q] = 0.f;

    int arow_l = tid >> 2, aseg = tid & 3;          // A: 128 rows x 4 segs
    int wrow_l = tid >> 1, wseg = (tid & 1) << 1;   // W: 256 rows x 2 segs each

    auto prefetch = [&](int c, int s) {
        int kk = c * 32;
        uint32_t st = sb + (uint32_t)s * STG_B;
        CP_ASYNC16(st + (uint32_t)(arow_l * 80 + aseg * 16),
                   g_Ah + (size_t)(R0 + arow_l) * KDIM + kk + aseg * 8);
        CP_ASYNC16(st + OFF_AL + (uint32_t)(arow_l * 80 + aseg * 16),
                   g_Al + (size_t)(R0 + arow_l) * KDIM + kk + aseg * 8);
        const __half* wp = g_W + (size_t)(n0 + wrow_l) * KDIM + kk + wseg * 8;
        uint32_t dw = st + OFF_W + (uint32_t)(wrow_l * 80 + wseg * 16);
        CP_ASYNC16(dw, wp);
        CP_ASYNC16(dw + 16, wp + 8);
    };

    prefetch(0, 0); CP_COMMIT();
    prefetch(1, 1); CP_COMMIT();

    int arow = warpM * 32 + (lane & 15);
    int acolh = (lane >> 4) << 3;
    int brow_b = warpN * 64 + ((lane >> 4) << 3) + (lane & 7);
    int bcolh = ((lane >> 3) & 1) << 3;

    for (int c = 0; c < 24; c++) {
        CP_WAIT1();
        __syncthreads();
        if (c + 2 < 24) { prefetch(c + 2, (c + 2) % 3); CP_COMMIT(); }
        uint32_t st = sb + (uint32_t)(c % 3) * STG_B;
#pragma unroll
        for (int ks = 0; ks < 2; ks++) {
            int k0 = ks * 16;
            uint32_t ah[2][4], al[2][4], bh[8][2];
#pragma unroll
            for (int mi = 0; mi < 2; mi++) {
                uint32_t off = (uint32_t)((arow + mi * 16) * 80 + (k0 + acolh) * 2);
                LDSM_X4(ah[mi][0], ah[mi][1], ah[mi][2], ah[mi][3], st + off);
                LDSM_X4(al[mi][0], al[mi][1], al[mi][2], al[mi][3], st + OFF_AL + off);
            }
#pragma unroll
            for (int nj = 0; nj < 4; nj++) {
                uint32_t off = (uint32_t)((brow_b + nj * 16) * 80 + (k0 + bcolh) * 2);
                uint32_t r0, r1, r2, r3;
                LDSM_X4(r0, r1, r2, r3, st + OFF_W + off);
                bh[nj * 2][0] = r0;     bh[nj * 2][1] = r1;
                bh[nj * 2 + 1][0] = r2; bh[nj * 2 + 1][1] = r3;
            }
#pragma unroll
            for (int mi = 0; mi < 2; mi++)
#pragma unroll
                for (int ni = 0; ni < 8; ni++) {
                    MMA16816(acc[mi][ni], ah[mi], bh[ni][0], bh[ni][1]);
                    MMA16816(acc[mi][ni], al[mi], bh[ni][0], bh[ni][1]);
                }
        }
        __syncthreads();
    }

    int erow = lane >> 2;
    int ecol = (lane & 3) << 1;
#pragma unroll
    for (int mi = 0; mi < 2; mi++) {
        int m0 = R0 + warpM * 32 + mi * 16 + erow;
#pragma unroll
        for (int ni = 0; ni < 8; ni++) {
            int n = n0 + warpN * 64 + ni * 8 + ecol;
            float b0 = bias[n], b1 = bias[n + 1];
            float2 v0, v1;
            v0.x = fmaxf(acc[mi][ni][0] + b0, 0.f);
            v0.y = fmaxf(acc[mi][ni][1] + b1, 0.f);
            v1.x = fmaxf(acc[mi][ni][2] + b0, 0.f);
            v1.y = fmaxf(acc[mi][ni][3] + b1, 0.f);
            int m1 = m0 + 8;
            *(float2*)&out[(size_t)m0 * N_HID + n] = v0;
            *(float2*)&out[(size_t)m1 * N_HID + n] = v1;
            if ((m0 & (S_LEN - 1)) == (S_LEN - 1)) {
                long long ti = (long long)M_ROWS * N_HID + (long long)(m0 >> 12) * N_HID + n;
                if (ti + 1 < out_size) *(float2*)&out[ti] = v0;
            }
            if ((m1 & (S_LEN - 1)) == (S_LEN - 1)) {
                long long ti = (long long)M_ROWS * N_HID + (long long)(m1 >> 12) * N_HID + n;
                if (ti + 1 < out_size) *(float2*)&out[ti] = v1;
            }
        }
    }
}

// ---------------- launch ----------------
extern "C" void kernel_launch(void* const* d_in, const int* in_sizes, int n_in,
                              void* d_out, int out_size) {
    const float *x = nullptr, *Wuw = nullptr, *Wub = nullptr, *Whw = nullptr,
                *Whb = nullptr, *H = nullptr;
    for (int i = 0; i < n_in; i++) {
        switch (in_sizes[i]) {
            case 16777216: x   = (const float*)d_in[i]; break;
            case 512:      Wuw = (const float*)d_in[i]; break;
            case 1:        Wub = (const float*)d_in[i]; break;
            case 786432:   Whw = (const float*)d_in[i]; break;
            case 1024:     Whb = (const float*)d_in[i]; break;
            case 1048576:  H   = (const float*)d_in[i]; break;
        }
    }
    float* out = (float*)d_out;

    static int s_attr_done = 0;
    if (!s_attr_done) {
        cudaFuncSetAttribute(k_tconv, cudaFuncAttributeMaxDynamicSharedMemorySize, CONV_SMEM);
        cudaFuncSetAttribute(k_mgemm, cudaFuncAttributeMaxDynamicSharedMemorySize, GSMEM);
        s_attr_done = 1;
    }

    __half *dW, *dH;
    cudaGetSymbolAddress((void**)&dW, g_W);
    cudaGetSymbolAddress((void**)&dH, g_H);

    k_u     <<<M_ROWS / 8, 256>>>(x, Wuw, Wub);
    k_cvt_x <<<M_ROWS * D_IN / 4 / 256, 256>>>(x);
    k_round <<<N_HID * KDIM / 4 / 256, 256>>>(Whw, dW);
    k_round <<<K_MEM * S_LEN / 4 / 256, 256>>>(H, dH);
    k_tconv <<<512, 256, CONV_SMEM>>>(nullptr);
    k_mgemm <<<dim3(N_HID / 256, M_ROWS / 128), 512, GSMEM>>>(Whb, out, (long long)out_size);
}